// round 1
// baseline (speedup 1.0000x reference)
#include <cuda_runtime.h>
#include <cstddef>

// ---------------------------------------------------------------------------
// Problem constants
// ---------------------------------------------------------------------------
#define BN 8
#define CH 64
#define HH 256
#define WW 256
#define NN 65536          // H*W
#define NCHUNK 32         // chunks per image for stage A/B (2048 pts each)
#define TPB 256

// ---------------------------------------------------------------------------
// Device scratch (static — no runtime allocation allowed)
// ---------------------------------------------------------------------------
__device__ float g_A[(size_t)BN * 128 * NN];            // concat branch outputs [b][128][N]
__device__ float g_partM[2][BN][NCHUNK][64 * 64];       // per-block partial K.V^T
__device__ float g_partKS[2][BN][NCHUNK][64];           // per-block partial ksum
__device__ float g_partVS[2][BN][NCHUNK][64];           // per-block partial vsum
__device__ float g_M2t[2][BN][64 * 64];                 // M2 transposed: [m][c]
__device__ float g_kse[2][BN][64];                      // ksum + eps
__device__ float g_u[2][BN][64];                        // r_w @ vsum

// ---------------------------------------------------------------------------
// Stage A: per-branch reductions. For each (b, chunk of 2048 points):
//   Kraw = Wk x + bk ; K = l2norm_cols(Kraw) ; Vraw = Wv x + bv
//   accumulate  matrix += K V^T,  ksum += sum K,  vsum += sum V
// Tiled: 32 tiles of 64 points. 256 threads, 4x4 register tiles.
// ---------------------------------------------------------------------------
#define A_SM_FLOATS 18692
#define A_SM_BYTES (A_SM_FLOATS * 4)

__global__ __launch_bounds__(256)
void stageA_kernel(const float* __restrict__ x,
                   const float* __restrict__ kw, const float* __restrict__ kb,
                   const float* __restrict__ vw, const float* __restrict__ vb,
                   int branch)
{
    extern __shared__ float sm[];
    float* sWkT = sm;              // [64k][68] transposed weights: WkT[ic][o]
    float* sWvT = sm + 4352;
    float* sXs  = sm + 8704;       // x tile [64ch][68]  (aliased as KT after GEMM1)
    float* sKT  = sXs;             // K transposed [64p][68]: KT[p][m]
    float* sVT  = sm + 13056;      // V transposed [64p][68]
    float* sRed = sm + 17408;      // 1088 floats: 16x68 norm partials / 64x17 final reduce
    float* sRn  = sm + 18496;      // 68
    float* sKb  = sm + 18564;      // 64
    float* sVb  = sm + 18628;      // 64

    const int tid = threadIdx.x;
    const int tx = tid & 15, ty = tid >> 4;
    const int r0 = ty * 4, cp = tx * 4;
    const int b = blockIdx.y, chunk = blockIdx.x;

    for (int e = tid; e < 4096; e += TPB) {
        int o = e >> 6, ic = e & 63;
        sWkT[ic * 68 + o] = kw[e];
        sWvT[ic * 68 + o] = vw[e];
    }
    if (tid < 64) { sKb[tid] = kb[tid]; sVb[tid] = vb[tid]; }

    float macc[4][4];
    float ksacc[4] = {0.f, 0.f, 0.f, 0.f};
    float vsacc[4] = {0.f, 0.f, 0.f, 0.f};
#pragma unroll
    for (int i = 0; i < 4; i++)
#pragma unroll
        for (int j = 0; j < 4; j++) macc[i][j] = 0.f;

    const float* xb = x + (size_t)b * CH * NN;
    __syncthreads();

    for (int t = 0; t < 32; t++) {
        const int n0 = chunk * 2048 + t * 64;
        // load x tile [64ch][64pts]
        for (int e = tid; e < 4096; e += TPB) {
            int ic = e >> 6, p = e & 63;
            sXs[ic * 68 + p] = xb[(size_t)ic * NN + n0 + p];
        }
        __syncthreads();

        // GEMM1: Kraw, Vraw (4x4 tiles, rows = out-channel, cols = point)
        float ka[4][4], va[4][4];
#pragma unroll
        for (int i = 0; i < 4; i++) {
            float kbv = sKb[r0 + i], vbv = sVb[r0 + i];
#pragma unroll
            for (int j = 0; j < 4; j++) { ka[i][j] = kbv; va[i][j] = vbv; }
        }
#pragma unroll 4
        for (int k = 0; k < 64; k++) {
            float4 xv = *(const float4*)&sXs[k * 68 + cp];
            float4 wk = *(const float4*)&sWkT[k * 68 + r0];
            float4 wv = *(const float4*)&sWvT[k * 68 + r0];
            float xr[4] = {xv.x, xv.y, xv.z, xv.w};
            float wkr[4] = {wk.x, wk.y, wk.z, wk.w};
            float wvr[4] = {wv.x, wv.y, wv.z, wv.w};
#pragma unroll
            for (int i = 0; i < 4; i++)
#pragma unroll
                for (int j = 0; j < 4; j++) {
                    ka[i][j] += wkr[i] * xr[j];
                    va[i][j] += wvr[i] * xr[j];
                }
        }

        // column (per-point) sum of squares of Kraw -> partial per ty
#pragma unroll
        for (int j = 0; j < 4; j++) {
            float s = ka[0][j] * ka[0][j] + ka[1][j] * ka[1][j]
                    + ka[2][j] * ka[2][j] + ka[3][j] * ka[3][j];
            sRed[ty * 68 + cp + j] = s;
        }
        __syncthreads();
        if (tid < 64) {
            float s = 0.f;
#pragma unroll
            for (int u2 = 0; u2 < 16; u2++) s += sRed[u2 * 68 + tid];
            sRn[tid] = rsqrtf(s);
        }
        __syncthreads();

        // normalize K, write KT/VT (KT aliases sXs; all reads done), accumulate sums
#pragma unroll
        for (int j = 0; j < 4; j++) {
            float rn = sRn[cp + j];
            float4 kv;
            kv.x = ka[0][j] * rn; kv.y = ka[1][j] * rn;
            kv.z = ka[2][j] * rn; kv.w = ka[3][j] * rn;
            *(float4*)&sKT[(cp + j) * 68 + r0] = kv;
            float4 vv;
            vv.x = va[0][j]; vv.y = va[1][j]; vv.z = va[2][j]; vv.w = va[3][j];
            *(float4*)&sVT[(cp + j) * 68 + r0] = vv;
            ksacc[0] += kv.x; ksacc[1] += kv.y; ksacc[2] += kv.z; ksacc[3] += kv.w;
            vsacc[0] += vv.x; vsacc[1] += vv.y; vsacc[2] += vv.z; vsacc[3] += vv.w;
        }
        __syncthreads();

        // GEMM2: matrix[m][c] += sum_p K[m][p] * V[c][p]
#pragma unroll 4
        for (int p = 0; p < 64; p++) {
            float4 kv = *(const float4*)&sKT[p * 68 + r0];
            float4 vv = *(const float4*)&sVT[p * 68 + cp];
            float kr[4] = {kv.x, kv.y, kv.z, kv.w};
            float vr[4] = {vv.x, vv.y, vv.z, vv.w};
#pragma unroll
            for (int i = 0; i < 4; i++)
#pragma unroll
                for (int j = 0; j < 4; j++)
                    macc[i][j] += kr[i] * vr[j];
        }
        __syncthreads();
    }

    // write partial matrix
    float* pm = &g_partM[branch][b][chunk][0];
#pragma unroll
    for (int i = 0; i < 4; i++)
#pragma unroll
        for (int j = 0; j < 4; j++)
            pm[(r0 + i) * 64 + cp + j] = macc[i][j];

    // reduce ksum/vsum across tx via smem (deterministic, no atomics)
#pragma unroll
    for (int i = 0; i < 4; i++) sRed[(r0 + i) * 17 + tx] = ksacc[i];
    __syncthreads();
    if (tid < 64) {
        float s = 0.f;
#pragma unroll
        for (int u2 = 0; u2 < 16; u2++) s += sRed[tid * 17 + u2];
        g_partKS[branch][b][chunk][tid] = s;
    }
    __syncthreads();
#pragma unroll
    for (int i = 0; i < 4; i++) sRed[(r0 + i) * 17 + tx] = vsacc[i];
    __syncthreads();
    if (tid < 64) {
        float s = 0.f;
#pragma unroll
        for (int u2 = 0; u2 < 16; u2++) s += sRed[tid * 17 + u2];
        g_partVS[branch][b][chunk][tid] = s;
    }
}

// ---------------------------------------------------------------------------
// Reduce/prep: sum partials over chunks, then
//   kse = ksum + EPS ; u = r_w @ vsum ; M2t[m][c] = sum_v r_w[c,v]*matrix[m,v]
// grid = 16 blocks (branch*8 + b)
// ---------------------------------------------------------------------------
__global__ __launch_bounds__(256)
void reduce_kernel(const float* __restrict__ rw1, const float* __restrict__ rw2)
{
    __shared__ float sM[4096];
    __shared__ float sVS[64];
    const int blk = blockIdx.x;
    const int branch = blk >> 3, b = blk & 7;
    const float* rw = branch ? rw2 : rw1;
    const int tid = threadIdx.x;

    for (int e = tid; e < 4096; e += 256) {
        float s = 0.f;
        for (int ch2 = 0; ch2 < NCHUNK; ch2++) s += g_partM[branch][b][ch2][e];
        sM[e] = s;
    }
    if (tid < 64) {
        float s = 0.f, v = 0.f;
        for (int ch2 = 0; ch2 < NCHUNK; ch2++) {
            s += g_partKS[branch][b][ch2][tid];
            v += g_partVS[branch][b][ch2][tid];
        }
        g_kse[branch][b][tid] = s + 1e-6f;
        sVS[tid] = v;
    }
    __syncthreads();

    for (int e = tid; e < 4096; e += 256) {
        int m = e >> 6, c = e & 63;
        float s = 0.f;
#pragma unroll 8
        for (int v = 0; v < 64; v++) s += rw[c * 64 + v] * sM[m * 64 + v];
        g_M2t[branch][b][e] = s;
    }
    if (tid < 64) {
        float s = 0.f;
#pragma unroll 8
        for (int v = 0; v < 64; v++) s += rw[tid * 64 + v] * sVS[v];
        g_u[branch][b][tid] = s;
    }
}

// ---------------------------------------------------------------------------
// Stage B: per point:
//   Q = l2norm(Wq x + bq) ; denom = 1/(N + Q . kse)
//   a[c] = denom*(u[c] + sum_m M2t[m][c]*Q[m]) + rb[c]   -> g_A[b][off+c][n]
// ---------------------------------------------------------------------------
#define B_SM_FLOATS 14536
#define B_SM_BYTES (B_SM_FLOATS * 4)

__global__ __launch_bounds__(256)
void stageB_kernel(const float* __restrict__ x,
                   const float* __restrict__ qw, const float* __restrict__ qb,
                   const float* __restrict__ rb, int branch)
{
    extern __shared__ float sm[];
    float* sWqT = sm;              // [64k][68] WqT[ic][o]
    float* sM2T = sm + 4352;       // [64m][68]: M2t[m][c]
    float* sXs  = sm + 8704;       // x tile / Q tile (row-major Q[m][p])
    float* sQs  = sXs;
    float* sRed = sm + 13056;      // 1088
    float* sRn  = sm + 14144;      // 68
    float* sDen = sm + 14212;      // 68
    float* sKse = sm + 14280;      // 64
    float* sU   = sm + 14344;      // 64
    float* sRb  = sm + 14408;      // 64
    float* sQb  = sm + 14472;      // 64

    const int tid = threadIdx.x;
    const int tx = tid & 15, ty = tid >> 4;
    const int r0 = ty * 4, cp = tx * 4;
    const int b = blockIdx.y, chunk = blockIdx.x;

    for (int e = tid; e < 4096; e += TPB) {
        int o = e >> 6, ic = e & 63;
        sWqT[ic * 68 + o] = qw[e];
        sM2T[(e >> 6) * 68 + (e & 63)] = g_M2t[branch][b][e];  // [m][c]
    }
    if (tid < 64) {
        sKse[tid] = g_kse[branch][b][tid];
        sU[tid]   = g_u[branch][b][tid];
        sRb[tid]  = rb[tid];
        sQb[tid]  = qb[tid];
    }

    const float* xb = x + (size_t)b * CH * NN;
    float* outb = g_A + ((size_t)b * 128 + (size_t)branch * 64) * NN;
    __syncthreads();

    for (int t = 0; t < 32; t++) {
        const int n0 = chunk * 2048 + t * 64;
        for (int e = tid; e < 4096; e += TPB) {
            int ic = e >> 6, p = e & 63;
            sXs[ic * 68 + p] = xb[(size_t)ic * NN + n0 + p];
        }
        __syncthreads();

        // GEMM1: Qraw
        float qa[4][4];
#pragma unroll
        for (int i = 0; i < 4; i++) {
            float qbv = sQb[r0 + i];
#pragma unroll
            for (int j = 0; j < 4; j++) qa[i][j] = qbv;
        }
#pragma unroll 4
        for (int k = 0; k < 64; k++) {
            float4 xv = *(const float4*)&sXs[k * 68 + cp];
            float4 wq = *(const float4*)&sWqT[k * 68 + r0];
            float xr[4] = {xv.x, xv.y, xv.z, xv.w};
            float wr[4] = {wq.x, wq.y, wq.z, wq.w};
#pragma unroll
            for (int i = 0; i < 4; i++)
#pragma unroll
                for (int j = 0; j < 4; j++)
                    qa[i][j] += wr[i] * xr[j];
        }

#pragma unroll
        for (int j = 0; j < 4; j++) {
            float s = qa[0][j] * qa[0][j] + qa[1][j] * qa[1][j]
                    + qa[2][j] * qa[2][j] + qa[3][j] * qa[3][j];
            sRed[ty * 68 + cp + j] = s;
        }
        __syncthreads();
        if (tid < 64) {
            float s = 0.f;
#pragma unroll
            for (int u2 = 0; u2 < 16; u2++) s += sRed[u2 * 68 + tid];
            sRn[tid] = rsqrtf(s);
        }
        __syncthreads();

        // write normalized Q row-major [m][p] (aliases sXs; reads done)
#pragma unroll
        for (int i = 0; i < 4; i++) {
            float4 qv;
            qv.x = qa[i][0] * sRn[cp + 0];
            qv.y = qa[i][1] * sRn[cp + 1];
            qv.z = qa[i][2] * sRn[cp + 2];
            qv.w = qa[i][3] * sRn[cp + 3];
            *(float4*)&sQs[(r0 + i) * 68 + cp] = qv;
        }
        __syncthreads();

        // denom per point
        if (tid < 64) {
            float s = 0.f;
#pragma unroll 8
            for (int m = 0; m < 64; m++) s += sQs[m * 68 + tid] * sKse[m];
            sDen[tid] = 1.0f / (65536.0f + s);
        }
        __syncthreads();

        // GEMM2: y[c][p] = sum_m M2t[m][c] * Q[m][p]
        float ya[4][4];
#pragma unroll
        for (int i = 0; i < 4; i++)
#pragma unroll
            for (int j = 0; j < 4; j++) ya[i][j] = 0.f;
#pragma unroll 4
        for (int m = 0; m < 64; m++) {
            float4 qv = *(const float4*)&sQs[m * 68 + cp];
            float4 mv = *(const float4*)&sM2T[m * 68 + r0];
            float qr[4] = {qv.x, qv.y, qv.z, qv.w};
            float mr[4] = {mv.x, mv.y, mv.z, mv.w};
#pragma unroll
            for (int i = 0; i < 4; i++)
#pragma unroll
                for (int j = 0; j < 4; j++)
                    ya[i][j] += mr[i] * qr[j];
        }

        // epilogue + store
#pragma unroll
        for (int i = 0; i < 4; i++) {
            const int c = r0 + i;
            const float uu = sU[c], rbv = sRb[c];
            float4 o;
            o.x = sDen[cp + 0] * (uu + ya[i][0]) + rbv;
            o.y = sDen[cp + 1] * (uu + ya[i][1]) + rbv;
            o.z = sDen[cp + 2] * (uu + ya[i][2]) + rbv;
            o.w = sDen[cp + 3] * (uu + ya[i][3]) + rbv;
            *(float4*)&outb[(size_t)c * NN + n0 + cp] = o;
        }
        __syncthreads();
    }
}

// ---------------------------------------------------------------------------
// Stage C: 3x3 conv, 128 -> 64 channels, SAME zero padding.
// Block: (b, 4 rows, 64 cols), all 64 out-channels. 8 chunks of 16 in-ch.
// Thread (tx in [0,16), tyO in [0,16)): 4 oc x 4 y x 4 x register tile.
// ---------------------------------------------------------------------------
#define CV_SM_FLOATS (6528 + 9216 + 64)
#define CV_SM_BYTES (CV_SM_FLOATS * 4)

__global__ __launch_bounds__(256)
void conv_kernel(const float* __restrict__ cw, const float* __restrict__ cb,
                 float* __restrict__ out)
{
    extern __shared__ float sm[];
    float* sIn = sm;               // [16ic][6 rows][68 (66 used)]
    float* sW  = sm + 6528;        // [64oc][16ic][9]
    float* sB  = sm + 15744;       // 64

    const int tid = threadIdx.x;
    const int tx = tid & 15, tyO = tid >> 4;
    const int oc0 = tyO * 4, xl = tx * 4;
    const int b = blockIdx.z;
    const int Y0 = blockIdx.y * 4;
    const int X0 = blockIdx.x * 64;

    if (tid < 64) sB[tid] = cb[tid];

    float acc[4][4][4];
#pragma unroll
    for (int i = 0; i < 4; i++)
#pragma unroll
        for (int y = 0; y < 4; y++)
#pragma unroll
            for (int j = 0; j < 4; j++) acc[i][y][j] = 0.f;

    const float* Ab = g_A + (size_t)b * 128 * NN;

    for (int cbk = 0; cbk < 8; cbk++) {
        __syncthreads();
        // input tile with halo (zero padded)
        for (int e = tid; e < 16 * 6 * 66; e += 256) {
            int ic = e / 396;
            int rr = (e / 66) % 6;
            int cc = e % 66;
            int gy = Y0 - 1 + rr;
            int gx = X0 - 1 + cc;
            float v = 0.f;
            if (gy >= 0 && gy < HH && gx >= 0 && gx < WW)
                v = Ab[(size_t)(cbk * 16 + ic) * NN + gy * WW + gx];
            sIn[(ic * 6 + rr) * 68 + cc] = v;
        }
        // weight chunk
        for (int e = tid; e < 9216; e += 256) {
            int k9 = e % 9;
            int t2 = e / 9;
            int ic = t2 & 15;
            int o = t2 >> 4;
            sW[e] = cw[(size_t)(o * 128 + cbk * 16 + ic) * 9 + k9];
        }
        __syncthreads();

        for (int ic = 0; ic < 16; ic++) {
#pragma unroll
            for (int ky = 0; ky < 3; ky++) {
                float wv[3][4];
#pragma unroll
                for (int kx = 0; kx < 3; kx++)
#pragma unroll
                    for (int i = 0; i < 4; i++)
                        wv[kx][i] = sW[((oc0 + i) * 16 + ic) * 9 + ky * 3 + kx];
#pragma unroll
                for (int yy = 0; yy < 4; yy++) {
                    const int rowb = (ic * 6 + yy + ky) * 68 + xl;
                    float4 iv4 = *(const float4*)&sIn[rowb];
                    float iv[6];
                    iv[0] = iv4.x; iv[1] = iv4.y; iv[2] = iv4.z; iv[3] = iv4.w;
                    iv[4] = sIn[rowb + 4];
                    iv[5] = sIn[rowb + 5];
#pragma unroll
                    for (int kx = 0; kx < 3; kx++)
#pragma unroll
                        for (int i = 0; i < 4; i++)
#pragma unroll
                            for (int j = 0; j < 4; j++)
                                acc[i][yy][j] += wv[kx][i] * iv[kx + j];
                }
            }
        }
    }

    // epilogue
#pragma unroll
    for (int i = 0; i < 4; i++) {
        float bv = sB[oc0 + i];
#pragma unroll
        for (int yy = 0; yy < 4; yy++) {
            float4 o;
            o.x = acc[i][yy][0] + bv;
            o.y = acc[i][yy][1] + bv;
            o.z = acc[i][yy][2] + bv;
            o.w = acc[i][yy][3] + bv;
            *(float4*)&out[((size_t)(b * 64 + oc0 + i)) * NN + (Y0 + yy) * WW + X0 + xl] = o;
        }
    }
}

// ---------------------------------------------------------------------------
// Launch
// ---------------------------------------------------------------------------
extern "C" void kernel_launch(void* const* d_in, const int* in_sizes, int n_in,
                              void* d_out, int out_size)
{
    (void)in_sizes; (void)n_in; (void)out_size;
    const float* t1  = (const float*)d_in[0];
    const float* t2  = (const float*)d_in[1];
    const float* q1w = (const float*)d_in[2];
    const float* q1b = (const float*)d_in[3];
    const float* k1w = (const float*)d_in[4];
    const float* k1b = (const float*)d_in[5];
    const float* v1w = (const float*)d_in[6];
    const float* v1b = (const float*)d_in[7];
    const float* r1w = (const float*)d_in[8];
    const float* r1b = (const float*)d_in[9];
    const float* q2w = (const float*)d_in[10];
    const float* q2b = (const float*)d_in[11];
    const float* k2w = (const float*)d_in[12];
    const float* k2b = (const float*)d_in[13];
    const float* v2w = (const float*)d_in[14];
    const float* v2b = (const float*)d_in[15];
    const float* r2w = (const float*)d_in[16];
    const float* r2b = (const float*)d_in[17];
    const float* cw  = (const float*)d_in[18];
    const float* cbp = (const float*)d_in[19];
    float* out = (float*)d_out;

    cudaFuncSetAttribute(stageA_kernel, cudaFuncAttributeMaxDynamicSharedMemorySize, A_SM_BYTES);
    cudaFuncSetAttribute(stageB_kernel, cudaFuncAttributeMaxDynamicSharedMemorySize, B_SM_BYTES);
    cudaFuncSetAttribute(conv_kernel,   cudaFuncAttributeMaxDynamicSharedMemorySize, CV_SM_BYTES);

    dim3 gAB(NCHUNK, BN);
    stageA_kernel<<<gAB, TPB, A_SM_BYTES>>>(t1, k1w, k1b, v1w, v1b, 0);
    stageA_kernel<<<gAB, TPB, A_SM_BYTES>>>(t2, k2w, k2b, v2w, v2b, 1);
    reduce_kernel<<<16, TPB>>>(r1w, r2w);
    stageB_kernel<<<gAB, TPB, B_SM_BYTES>>>(t1, q1w, q1b, r1b, 0);
    stageB_kernel<<<gAB, TPB, B_SM_BYTES>>>(t2, q2w, q2b, r2b, 1);
    conv_kernel<<<dim3(WW / 64, HH / 4, BN), TPB, CV_SM_BYTES>>>(cw, cbp, out);
}

// round 2
// speedup vs baseline: 1.3411x; 1.3411x over previous
#include <cuda_runtime.h>
#include <cstdint>
#include <cstddef>

// ---------------------------------------------------------------------------
// Problem constants
// ---------------------------------------------------------------------------
#define BN 8
#define CH 64
#define HH 256
#define WW 256
#define NN 65536          // H*W
#define NCHUNK 64         // chunks per image for stage A/B (1024 pts each)
#define CHUNK_PTS 1024
#define TILES 16          // 64-pt tiles per chunk
#define TPB 256

// ---------------------------------------------------------------------------
// Device scratch (static — no runtime allocation allowed)
// ---------------------------------------------------------------------------
__device__ float g_A[(size_t)BN * 128 * NN];            // concat branch outputs [b][128][N]
__device__ float g_partM[2][BN][NCHUNK][64 * 64];       // per-block partial K.V^T
__device__ float g_partKS[2][BN][NCHUNK][64];           // per-block partial ksum
__device__ float g_partVS[2][BN][NCHUNK][64];           // per-block partial vsum
__device__ float g_M2t[2][BN][64 * 64];                 // M2 transposed: [m][c]
__device__ float g_kse[2][BN][64];                      // ksum + eps
__device__ float g_u[2][BN][64];                        // r_w @ vsum

// ---------------------------------------------------------------------------
// tf32 helpers
// ---------------------------------------------------------------------------
__device__ __forceinline__ float to_tf32(float f) {
    uint32_t u;
    asm("cvt.rna.tf32.f32 %0, %1;" : "=r"(u) : "f"(f));
    return __uint_as_float(u);
}

__device__ __forceinline__ void mma_tf32(float* c,
                                         uint32_t a0, uint32_t a1, uint32_t a2, uint32_t a3,
                                         uint32_t b0, uint32_t b1) {
    asm volatile(
        "mma.sync.aligned.m16n8k8.row.col.f32.tf32.tf32.f32 "
        "{%0,%1,%2,%3}, {%4,%5,%6,%7}, {%8,%9}, {%0,%1,%2,%3};"
        : "+f"(c[0]), "+f"(c[1]), "+f"(c[2]), "+f"(c[3])
        : "r"(a0), "r"(a1), "r"(a2), "r"(a3), "r"(b0), "r"(b1));
}

// ---------------------------------------------------------------------------
// Stage A: per-branch reductions. For each (b, chunk of 1024 points):
//   Kraw = Wk x + bk ; K = l2norm_cols(Kraw) ; Vraw = Wv x + bv
//   accumulate  matrix += K V^T,  ksum += sum K,  vsum += sum V
// ---------------------------------------------------------------------------
#define A_SM_FLOATS 18692
#define A_SM_BYTES (A_SM_FLOATS * 4)

__global__ __launch_bounds__(256)
void stageA_kernel(const float* __restrict__ x,
                   const float* __restrict__ kw, const float* __restrict__ kb,
                   const float* __restrict__ vw, const float* __restrict__ vb,
                   int branch)
{
    extern __shared__ float sm[];
    float* sWkT = sm;              // [64k][68] transposed weights: WkT[ic][o]
    float* sWvT = sm + 4352;
    float* sXs  = sm + 8704;       // x tile [64ch][68]  (aliased as KT after GEMM1)
    float* sKT  = sXs;             // K transposed [64p][68]: KT[p][m]
    float* sVT  = sm + 13056;      // V transposed [64p][68]
    float* sRed = sm + 17408;      // 1088 floats
    float* sRn  = sm + 18496;      // 68
    float* sKb  = sm + 18564;      // 64
    float* sVb  = sm + 18628;      // 64

    const int tid = threadIdx.x;
    const int tx = tid & 15, ty = tid >> 4;
    const int r0 = ty * 4, cp = tx * 4;
    const int b = blockIdx.y, chunk = blockIdx.x;

    for (int e = tid; e < 4096; e += TPB) {
        int o = e >> 6, ic = e & 63;
        sWkT[ic * 68 + o] = kw[e];
        sWvT[ic * 68 + o] = vw[e];
    }
    if (tid < 64) { sKb[tid] = kb[tid]; sVb[tid] = vb[tid]; }

    float macc[4][4];
    float ksacc[4] = {0.f, 0.f, 0.f, 0.f};
    float vsacc[4] = {0.f, 0.f, 0.f, 0.f};
#pragma unroll
    for (int i = 0; i < 4; i++)
#pragma unroll
        for (int j = 0; j < 4; j++) macc[i][j] = 0.f;

    const float* xb = x + (size_t)b * CH * NN;
    __syncthreads();

    for (int t = 0; t < TILES; t++) {
        const int n0 = chunk * CHUNK_PTS + t * 64;
        for (int e = tid; e < 4096; e += TPB) {
            int ic = e >> 6, p = e & 63;
            sXs[ic * 68 + p] = xb[(size_t)ic * NN + n0 + p];
        }
        __syncthreads();

        float ka[4][4], va[4][4];
#pragma unroll
        for (int i = 0; i < 4; i++) {
            float kbv = sKb[r0 + i], vbv = sVb[r0 + i];
#pragma unroll
            for (int j = 0; j < 4; j++) { ka[i][j] = kbv; va[i][j] = vbv; }
        }
#pragma unroll 4
        for (int k = 0; k < 64; k++) {
            float4 xv = *(const float4*)&sXs[k * 68 + cp];
            float4 wk = *(const float4*)&sWkT[k * 68 + r0];
            float4 wv = *(const float4*)&sWvT[k * 68 + r0];
            float xr[4] = {xv.x, xv.y, xv.z, xv.w};
            float wkr[4] = {wk.x, wk.y, wk.z, wk.w};
            float wvr[4] = {wv.x, wv.y, wv.z, wv.w};
#pragma unroll
            for (int i = 0; i < 4; i++)
#pragma unroll
                for (int j = 0; j < 4; j++) {
                    ka[i][j] += wkr[i] * xr[j];
                    va[i][j] += wvr[i] * xr[j];
                }
        }

#pragma unroll
        for (int j = 0; j < 4; j++) {
            float s = ka[0][j] * ka[0][j] + ka[1][j] * ka[1][j]
                    + ka[2][j] * ka[2][j] + ka[3][j] * ka[3][j];
            sRed[ty * 68 + cp + j] = s;
        }
        __syncthreads();
        if (tid < 64) {
            float s = 0.f;
#pragma unroll
            for (int u2 = 0; u2 < 16; u2++) s += sRed[u2 * 68 + tid];
            sRn[tid] = rsqrtf(s);
        }
        __syncthreads();

#pragma unroll
        for (int j = 0; j < 4; j++) {
            float rn = sRn[cp + j];
            float4 kv;
            kv.x = ka[0][j] * rn; kv.y = ka[1][j] * rn;
            kv.z = ka[2][j] * rn; kv.w = ka[3][j] * rn;
            *(float4*)&sKT[(cp + j) * 68 + r0] = kv;
            float4 vv;
            vv.x = va[0][j]; vv.y = va[1][j]; vv.z = va[2][j]; vv.w = va[3][j];
            *(float4*)&sVT[(cp + j) * 68 + r0] = vv;
            ksacc[0] += kv.x; ksacc[1] += kv.y; ksacc[2] += kv.z; ksacc[3] += kv.w;
            vsacc[0] += vv.x; vsacc[1] += vv.y; vsacc[2] += vv.z; vsacc[3] += vv.w;
        }
        __syncthreads();

#pragma unroll 4
        for (int p = 0; p < 64; p++) {
            float4 kv = *(const float4*)&sKT[p * 68 + r0];
            float4 vv = *(const float4*)&sVT[p * 68 + cp];
            float kr[4] = {kv.x, kv.y, kv.z, kv.w};
            float vr[4] = {vv.x, vv.y, vv.z, vv.w};
#pragma unroll
            for (int i = 0; i < 4; i++)
#pragma unroll
                for (int j = 0; j < 4; j++)
                    macc[i][j] += kr[i] * vr[j];
        }
        __syncthreads();
    }

    float* pm = &g_partM[branch][b][chunk][0];
#pragma unroll
    for (int i = 0; i < 4; i++)
#pragma unroll
        for (int j = 0; j < 4; j++)
            pm[(r0 + i) * 64 + cp + j] = macc[i][j];

#pragma unroll
    for (int i = 0; i < 4; i++) sRed[(r0 + i) * 17 + tx] = ksacc[i];
    __syncthreads();
    if (tid < 64) {
        float s = 0.f;
#pragma unroll
        for (int u2 = 0; u2 < 16; u2++) s += sRed[tid * 17 + u2];
        g_partKS[branch][b][chunk][tid] = s;
    }
    __syncthreads();
#pragma unroll
    for (int i = 0; i < 4; i++) sRed[(r0 + i) * 17 + tx] = vsacc[i];
    __syncthreads();
    if (tid < 64) {
        float s = 0.f;
#pragma unroll
        for (int u2 = 0; u2 < 16; u2++) s += sRed[tid * 17 + u2];
        g_partVS[branch][b][chunk][tid] = s;
    }
}

// ---------------------------------------------------------------------------
// Reduce/prep
// ---------------------------------------------------------------------------
__global__ __launch_bounds__(256)
void reduce_kernel(const float* __restrict__ rw1, const float* __restrict__ rw2)
{
    __shared__ float sM[4096];
    __shared__ float sVS[64];
    const int blk = blockIdx.x;
    const int branch = blk >> 3, b = blk & 7;
    const float* rw = branch ? rw2 : rw1;
    const int tid = threadIdx.x;

    for (int e = tid; e < 4096; e += 256) {
        float s = 0.f;
        for (int ch2 = 0; ch2 < NCHUNK; ch2++) s += g_partM[branch][b][ch2][e];
        sM[e] = s;
    }
    if (tid < 64) {
        float s = 0.f, v = 0.f;
        for (int ch2 = 0; ch2 < NCHUNK; ch2++) {
            s += g_partKS[branch][b][ch2][tid];
            v += g_partVS[branch][b][ch2][tid];
        }
        g_kse[branch][b][tid] = s + 1e-6f;
        sVS[tid] = v;
    }
    __syncthreads();

    for (int e = tid; e < 4096; e += 256) {
        int m = e >> 6, c = e & 63;
        float s = 0.f;
#pragma unroll 8
        for (int v = 0; v < 64; v++) s += rw[c * 64 + v] * sM[m * 64 + v];
        g_M2t[branch][b][e] = s;
    }
    if (tid < 64) {
        float s = 0.f;
#pragma unroll 8
        for (int v = 0; v < 64; v++) s += rw[tid * 64 + v] * sVS[v];
        g_u[branch][b][tid] = s;
    }
}

// ---------------------------------------------------------------------------
// Stage B
// ---------------------------------------------------------------------------
#define B_SM_FLOATS 14536
#define B_SM_BYTES (B_SM_FLOATS * 4)

__global__ __launch_bounds__(256)
void stageB_kernel(const float* __restrict__ x,
                   const float* __restrict__ qw, const float* __restrict__ qb,
                   const float* __restrict__ rb, int branch)
{
    extern __shared__ float sm[];
    float* sWqT = sm;              // [64k][68]
    float* sM2T = sm + 4352;       // [64m][68]
    float* sXs  = sm + 8704;
    float* sQs  = sXs;
    float* sRed = sm + 13056;
    float* sRn  = sm + 14144;
    float* sDen = sm + 14212;
    float* sKse = sm + 14280;
    float* sU   = sm + 14344;
    float* sRb  = sm + 14408;
    float* sQb  = sm + 14472;

    const int tid = threadIdx.x;
    const int tx = tid & 15, ty = tid >> 4;
    const int r0 = ty * 4, cp = tx * 4;
    const int b = blockIdx.y, chunk = blockIdx.x;

    for (int e = tid; e < 4096; e += TPB) {
        int o = e >> 6, ic = e & 63;
        sWqT[ic * 68 + o] = qw[e];
        sM2T[(e >> 6) * 68 + (e & 63)] = g_M2t[branch][b][e];
    }
    if (tid < 64) {
        sKse[tid] = g_kse[branch][b][tid];
        sU[tid]   = g_u[branch][b][tid];
        sRb[tid]  = rb[tid];
        sQb[tid]  = qb[tid];
    }

    const float* xb = x + (size_t)b * CH * NN;
    float* outb = g_A + ((size_t)b * 128 + (size_t)branch * 64) * NN;
    __syncthreads();

    for (int t = 0; t < TILES; t++) {
        const int n0 = chunk * CHUNK_PTS + t * 64;
        for (int e = tid; e < 4096; e += TPB) {
            int ic = e >> 6, p = e & 63;
            sXs[ic * 68 + p] = xb[(size_t)ic * NN + n0 + p];
        }
        __syncthreads();

        float qa[4][4];
#pragma unroll
        for (int i = 0; i < 4; i++) {
            float qbv = sQb[r0 + i];
#pragma unroll
            for (int j = 0; j < 4; j++) qa[i][j] = qbv;
        }
#pragma unroll 4
        for (int k = 0; k < 64; k++) {
            float4 xv = *(const float4*)&sXs[k * 68 + cp];
            float4 wq = *(const float4*)&sWqT[k * 68 + r0];
            float xr[4] = {xv.x, xv.y, xv.z, xv.w};
            float wr[4] = {wq.x, wq.y, wq.z, wq.w};
#pragma unroll
            for (int i = 0; i < 4; i++)
#pragma unroll
                for (int j = 0; j < 4; j++)
                    qa[i][j] += wr[i] * xr[j];
        }

#pragma unroll
        for (int j = 0; j < 4; j++) {
            float s = qa[0][j] * qa[0][j] + qa[1][j] * qa[1][j]
                    + qa[2][j] * qa[2][j] + qa[3][j] * qa[3][j];
            sRed[ty * 68 + cp + j] = s;
        }
        __syncthreads();
        if (tid < 64) {
            float s = 0.f;
#pragma unroll
            for (int u2 = 0; u2 < 16; u2++) s += sRed[u2 * 68 + tid];
            sRn[tid] = rsqrtf(s);
        }
        __syncthreads();

#pragma unroll
        for (int i = 0; i < 4; i++) {
            float4 qv;
            qv.x = qa[i][0] * sRn[cp + 0];
            qv.y = qa[i][1] * sRn[cp + 1];
            qv.z = qa[i][2] * sRn[cp + 2];
            qv.w = qa[i][3] * sRn[cp + 3];
            *(float4*)&sQs[(r0 + i) * 68 + cp] = qv;
        }
        __syncthreads();

        if (tid < 64) {
            float s = 0.f;
#pragma unroll 8
            for (int m = 0; m < 64; m++) s += sQs[m * 68 + tid] * sKse[m];
            sDen[tid] = 1.0f / (65536.0f + s);
        }
        __syncthreads();

        float ya[4][4];
#pragma unroll
        for (int i = 0; i < 4; i++)
#pragma unroll
            for (int j = 0; j < 4; j++) ya[i][j] = 0.f;
#pragma unroll 4
        for (int m = 0; m < 64; m++) {
            float4 qv = *(const float4*)&sQs[m * 68 + cp];
            float4 mv = *(const float4*)&sM2T[m * 68 + r0];
            float qr[4] = {qv.x, qv.y, qv.z, qv.w};
            float mr[4] = {mv.x, mv.y, mv.z, mv.w};
#pragma unroll
            for (int i = 0; i < 4; i++)
#pragma unroll
                for (int j = 0; j < 4; j++)
                    ya[i][j] += mr[i] * qr[j];
        }

#pragma unroll
        for (int i = 0; i < 4; i++) {
            const int c = r0 + i;
            const float uu = sU[c], rbv = sRb[c];
            float4 o;
            o.x = sDen[cp + 0] * (uu + ya[i][0]) + rbv;
            o.y = sDen[cp + 1] * (uu + ya[i][1]) + rbv;
            o.z = sDen[cp + 2] * (uu + ya[i][2]) + rbv;
            o.w = sDen[cp + 3] * (uu + ya[i][3]) + rbv;
            *(float4*)&outb[(size_t)c * NN + n0 + cp] = o;
        }
        __syncthreads();
    }
}

// ---------------------------------------------------------------------------
// Stage C: 3x3 conv, 128 -> 64 channels, SAME padding — tf32 mma.sync.
// Block: batch b, 2 rows x 64 cols = 128 points (N), all 64 oc (M), K=1152.
// 8 warps: warpM = warp&3 (16-oc strip), warpN = warp>>2 (row 0/1).
// Each warp: 8 m16n8 accumulator tiles over its 64-pt row.
// smem: sIn [16ic][296] (4 rows x 68 used; 296 stride => conflict-free
//       B-fragment gathers: bank = (8*... ) all 32 lanes distinct),
//       sW [64oc][145] (144 = 16ic*9 used), sB [64].
// ---------------------------------------------------------------------------
#define CV_SM_FLOATS (16 * 296 + 64 * 145 + 64)   // 14080
#define CV_SM_BYTES (CV_SM_FLOATS * 4)

__global__ __launch_bounds__(256)
void conv_mma_kernel(const float* __restrict__ cw, const float* __restrict__ cb,
                     float* __restrict__ out)
{
    extern __shared__ float sm[];
    float* sIn = sm;                  // 16 * 296
    float* sW  = sm + 16 * 296;       // 64 * 145
    float* sB  = sm + 16 * 296 + 64 * 145;

    const int tid  = threadIdx.x;
    const int lane = tid & 31, warp = tid >> 5;
    const int warpM = warp & 3, warpN = warp >> 2;
    const int oc0 = warpM * 16;
    const int g = lane >> 2, tg = lane & 3;     // mma groupID / threadInGroup
    const int b  = blockIdx.z;
    const int Y0 = blockIdx.y * 2;
    const int X0 = blockIdx.x * 64;

    if (tid < 64) sB[tid] = cb[tid];

    float acc[8][4];
#pragma unroll
    for (int nt = 0; nt < 8; nt++)
#pragma unroll
        for (int i = 0; i < 4; i++) acc[nt][i] = 0.f;

    const float* Ab = g_A + (size_t)b * 128 * NN;

    for (int cbk = 0; cbk < 8; cbk++) {
        __syncthreads();
        // input tile: 16 ic x 4 rows x 66 cols (halo, zero padded), tf32-converted
        for (int e = tid; e < 16 * 4 * 66; e += 256) {
            int ic = e / 264;
            int rr = (e / 66) & 3;
            int cc = e % 66;
            int gy = Y0 - 1 + rr, gx = X0 - 1 + cc;
            float v = 0.f;
            if (gy >= 0 && gy < HH && gx >= 0 && gx < WW)
                v = Ab[(size_t)(cbk * 16 + ic) * NN + gy * WW + gx];
            sIn[ic * 296 + rr * 68 + cc] = to_tf32(v);
        }
        // weights: sW[oc][ic*9+off]
        for (int e = tid; e < 9216; e += 256) {
            int k9 = e % 9;
            int t2 = e / 9;
            int ic = t2 & 15, o = t2 >> 4;
            sW[o * 145 + ic * 9 + k9] =
                to_tf32(cw[(size_t)(o * 128 + cbk * 16 + ic) * 9 + k9]);
        }
        __syncthreads();

#pragma unroll
        for (int ky = 0; ky < 3; ky++) {
#pragma unroll
            for (int kx = 0; kx < 3; kx++) {
                const int off = ky * 3 + kx;
#pragma unroll
                for (int ks = 0; ks < 2; ks++) {
                    const int icb = ks * 8;
                    // A fragment (weights, row-major m16 x k8)
                    const int wr0 = (oc0 + g) * 145 + (icb + tg) * 9 + off;
                    uint32_t a0 = __float_as_uint(sW[wr0]);
                    uint32_t a1 = __float_as_uint(sW[wr0 + 8 * 145]);
                    uint32_t a2 = __float_as_uint(sW[wr0 + 36]);            // +4 ic
                    uint32_t a3 = __float_as_uint(sW[wr0 + 8 * 145 + 36]);
                    // B fragments (input, k8 x n8 col-major)
                    const float* inb = &sIn[(icb + tg) * 296 + (warpN + ky) * 68 + kx + g];
#pragma unroll
                    for (int nt = 0; nt < 8; nt++) {
                        uint32_t b0 = __float_as_uint(inb[nt * 8]);
                        uint32_t b1 = __float_as_uint(inb[nt * 8 + 4 * 296]);
                        mma_tf32(acc[nt], a0, a1, a2, a3, b0, b1);
                    }
                }
            }
        }
    }

    // epilogue: c0,c1 -> (oc0+g, cols 2tg,2tg+1); c2,c3 -> row +8
    const int yg = Y0 + warpN;
#pragma unroll
    for (int nt = 0; nt < 8; nt++) {
        const int xg = X0 + nt * 8 + tg * 2;
        const float bv0 = sB[oc0 + g];
        const float bv1 = sB[oc0 + g + 8];
        float2 o0, o1;
        o0.x = acc[nt][0] + bv0; o0.y = acc[nt][1] + bv0;
        o1.x = acc[nt][2] + bv1; o1.y = acc[nt][3] + bv1;
        *(float2*)&out[((size_t)(b * 64 + oc0 + g)) * NN + yg * WW + xg] = o0;
        *(float2*)&out[((size_t)(b * 64 + oc0 + g + 8)) * NN + yg * WW + xg] = o1;
    }
}

// ---------------------------------------------------------------------------
// Launch
// ---------------------------------------------------------------------------
extern "C" void kernel_launch(void* const* d_in, const int* in_sizes, int n_in,
                              void* d_out, int out_size)
{
    (void)in_sizes; (void)n_in; (void)out_size;
    const float* t1  = (const float*)d_in[0];
    const float* t2  = (const float*)d_in[1];
    const float* q1w = (const float*)d_in[2];
    const float* q1b = (const float*)d_in[3];
    const float* k1w = (const float*)d_in[4];
    const float* k1b = (const float*)d_in[5];
    const float* v1w = (const float*)d_in[6];
    const float* v1b = (const float*)d_in[7];
    const float* r1w = (const float*)d_in[8];
    const float* r1b = (const float*)d_in[9];
    const float* q2w = (const float*)d_in[10];
    const float* q2b = (const float*)d_in[11];
    const float* k2w = (const float*)d_in[12];
    const float* k2b = (const float*)d_in[13];
    const float* v2w = (const float*)d_in[14];
    const float* v2b = (const float*)d_in[15];
    const float* r2w = (const float*)d_in[16];
    const float* r2b = (const float*)d_in[17];
    const float* cw  = (const float*)d_in[18];
    const float* cbp = (const float*)d_in[19];
    float* out = (float*)d_out;

    cudaFuncSetAttribute(stageA_kernel,   cudaFuncAttributeMaxDynamicSharedMemorySize, A_SM_BYTES);
    cudaFuncSetAttribute(stageB_kernel,   cudaFuncAttributeMaxDynamicSharedMemorySize, B_SM_BYTES);
    cudaFuncSetAttribute(conv_mma_kernel, cudaFuncAttributeMaxDynamicSharedMemorySize, CV_SM_BYTES);

    dim3 gAB(NCHUNK, BN);
    stageA_kernel<<<gAB, TPB, A_SM_BYTES>>>(t1, k1w, k1b, v1w, v1b, 0);
    stageA_kernel<<<gAB, TPB, A_SM_BYTES>>>(t2, k2w, k2b, v2w, v2b, 1);
    reduce_kernel<<<16, TPB>>>(r1w, r2w);
    stageB_kernel<<<gAB, TPB, B_SM_BYTES>>>(t1, q1w, q1b, r1b, 0);
    stageB_kernel<<<gAB, TPB, B_SM_BYTES>>>(t2, q2w, q2b, r2b, 1);
    conv_mma_kernel<<<dim3(WW / 64, HH / 2, BN), TPB, CV_SM_BYTES>>>(cw, cbp, out);
}